// round 1
// baseline (speedup 1.0000x reference)
#include <cuda_runtime.h>
#include <math.h>

#define Bn 131072
#define Dd 256
#define Hh 256
#define Cc 8

// Scratch (device globals — no allocations allowed)
__device__ int g_cnt[Cc];            // per-expert routed count
__device__ int g_idx[Cc * Bn];       // per-expert compacted sample indices

__global__ void zero_cnt_kernel() {
    if (threadIdx.x < Cc) g_cnt[threadIdx.x] = 0;
}

// ---------------------------------------------------------------------------
// 64x256 fp32 GEMM tile: Out[rows,256] = relu(A[rows,256] @ W[256,256] + bias)
// BM=64, BN=256 (full width -> one block owns its output rows completely),
// BK=16, 256 threads, 8x8 per-thread microtile.
// GATHER: rows come from per-expert compacted index list; A==Out aliasing is
// safe because each routed row is read+written by exactly one block, and all
// reads complete before the epilogue stores.
// ---------------------------------------------------------------------------
template<bool GATHER>
__global__ __launch_bounds__(256, 2)
void gemm64x256_relu(const float* A,
                     const float* __restrict__ Wall,
                     const float* __restrict__ ball,
                     float* Out)
{
    __shared__ float As[16][64];
    __shared__ float Bs[16][256];
    __shared__ int   ridx[64];

    const int tid   = threadIdx.x;
    const int mBase = blockIdx.y * 64;

    const float* W;
    const float* bias;
    if (GATHER) {
        const int c   = blockIdx.z;
        const int cnt = g_cnt[c];
        if (mBase >= cnt) return;
        if (tid < 64) {
            int gi = mBase + tid;
            ridx[tid] = (gi < cnt) ? g_idx[c * Bn + gi] : -1;
        }
        W    = Wall + (size_t)c * Hh * Hh;
        bias = ball + c * Hh;
        __syncthreads();
    } else {
        W    = Wall;
        bias = ball;
    }

    const int tx = tid & 31;   // n-dir: cols tx*4..+3 and 128+tx*4..+3
    const int ty = tid >> 5;   // m-dir: rows ty*8..+7

    // A-tile load mapping: one float4 per thread per k-step
    const int arow = tid >> 2;           // 0..63
    const int ac4  = (tid & 3) * 4;      // 0,4,8,12
    const int grow = GATHER ? ridx[arow] : (mBase + arow);
    const float* aptr = A + (size_t)(grow > 0 ? grow : 0) * 256 + ac4;

    float acc[8][8];
    #pragma unroll
    for (int i = 0; i < 8; i++)
        #pragma unroll
        for (int j = 0; j < 8; j++) acc[i][j] = 0.f;

    for (int kb = 0; kb < 256; kb += 16) {
        float4 av = make_float4(0.f, 0.f, 0.f, 0.f);
        if (!GATHER || grow >= 0) av = *(const float4*)(aptr + kb);
        As[ac4 + 0][arow] = av.x;
        As[ac4 + 1][arow] = av.y;
        As[ac4 + 2][arow] = av.z;
        As[ac4 + 3][arow] = av.w;
        #pragma unroll
        for (int i = 0; i < 4; i++) {
            int v  = tid + i * 256;
            int br = v >> 6;
            int bc = (v & 63) * 4;
            *(float4*)&Bs[br][bc] = *(const float4*)(W + (size_t)(kb + br) * 256 + bc);
        }
        __syncthreads();
        #pragma unroll
        for (int k = 0; k < 16; k++) {
            float a[8], b[8];
            *(float4*)(a)     = *(const float4*)&As[k][ty * 8];
            *(float4*)(a + 4) = *(const float4*)&As[k][ty * 8 + 4];
            *(float4*)(b)     = *(const float4*)&Bs[k][tx * 4];
            *(float4*)(b + 4) = *(const float4*)&Bs[k][128 + tx * 4];
            #pragma unroll
            for (int i = 0; i < 8; i++)
                #pragma unroll
                for (int j = 0; j < 8; j++)
                    acc[i][j] += a[i] * b[j];
        }
        __syncthreads();
    }

    float bv[8];
    #pragma unroll
    for (int j = 0; j < 4; j++) {
        bv[j]     = bias[tx * 4 + j];
        bv[4 + j] = bias[128 + tx * 4 + j];
    }

    #pragma unroll
    for (int i = 0; i < 8; i++) {
        int row = GATHER ? ridx[ty * 8 + i] : (mBase + ty * 8 + i);
        if (GATHER && row < 0) continue;
        float4 o0, o1;
        o0.x = fmaxf(acc[i][0] + bv[0], 0.f);
        o0.y = fmaxf(acc[i][1] + bv[1], 0.f);
        o0.z = fmaxf(acc[i][2] + bv[2], 0.f);
        o0.w = fmaxf(acc[i][3] + bv[3], 0.f);
        o1.x = fmaxf(acc[i][4] + bv[4], 0.f);
        o1.y = fmaxf(acc[i][5] + bv[5], 0.f);
        o1.z = fmaxf(acc[i][6] + bv[6], 0.f);
        o1.w = fmaxf(acc[i][7] + bv[7], 0.f);
        float* op = Out + (size_t)row * 256;
        *(float4*)(op + tx * 4)       = o0;
        *(float4*)(op + 128 + tx * 4) = o1;
    }
}

// ---------------------------------------------------------------------------
// Head + routing: warp per sample. logits = h@W2+b2, softmax, per-class tau
// masked argmax, compaction of routed samples into per-expert lists.
// ---------------------------------------------------------------------------
__global__ __launch_bounds__(256)
void head_route(const float* __restrict__ Hbuf,
                const float* __restrict__ W2, const float* __restrict__ b2,
                const float* __restrict__ tau,
                float* __restrict__ outLogits, float* __restrict__ outDepth)
{
    __shared__ float Wst[8][256];   // transposed W2 -> conflict-free reads
    __shared__ float b2s[8], taus[8];
    const int tid = threadIdx.x;
    for (int idx = tid; idx < 2048; idx += 256) {
        int k = idx >> 3, j = idx & 7;
        Wst[j][k] = W2[idx];
    }
    if (tid < 8) { b2s[tid] = b2[tid]; taus[tid] = tau[tid]; }
    __syncthreads();

    const int warp = tid >> 5, lane = tid & 31;
    const int s = blockIdx.x * 8 + warp;
    const float* hrow = Hbuf + (size_t)s * 256;

    float acc[8];
    #pragma unroll
    for (int j = 0; j < 8; j++) acc[j] = 0.f;
    #pragma unroll
    for (int kk = 0; kk < 256; kk += 32) {
        float hv = hrow[kk + lane];
        #pragma unroll
        for (int j = 0; j < 8; j++) acc[j] += hv * Wst[j][kk + lane];
    }
    #pragma unroll
    for (int j = 0; j < 8; j++)
        #pragma unroll
        for (int off = 16; off; off >>= 1)
            acc[j] += __shfl_down_sync(0xffffffffu, acc[j], off);

    if (lane == 0) {
        float lg[8], e[8];
        float mx = -1e30f;
        #pragma unroll
        for (int j = 0; j < 8; j++) { lg[j] = acc[j] + b2s[j]; mx = fmaxf(mx, lg[j]); }
        float ssum = 0.f;
        #pragma unroll
        for (int j = 0; j < 8; j++) { e[j] = expf(lg[j] - mx); ssum += e[j]; }
        float inv = 1.0f / ssum;
        int best = -1; float bp = -1.f;
        #pragma unroll
        for (int j = 0; j < 8; j++) {
            float pj = e[j] * inv;
            if (pj >= taus[j] && pj > bp) { bp = pj; best = j; }
        }
        float* lo = outLogits + (size_t)s * 8;
        #pragma unroll
        for (int j = 0; j < 8; j++) lo[j] = lg[j];
        outDepth[s] = (best >= 0) ? 1.0f : 0.0f;
        if (best >= 0) {
            int pos = atomicAdd(&g_cnt[best], 1);
            g_idx[best * Bn + pos] = s;
        }
    }
}

// ---------------------------------------------------------------------------
// Expert head: per-expert tiles over compacted lists. h_c row (already in
// Hbuf) @ Wc2[c] + bc2[c] -> overwrite out_logits for routed samples.
// ---------------------------------------------------------------------------
__global__ __launch_bounds__(256)
void expert_head(const float* __restrict__ Hbuf,
                 const float* __restrict__ Wc2, const float* __restrict__ bc2,
                 float* __restrict__ outLogits)
{
    const int c    = blockIdx.z;
    const int cnt  = g_cnt[c];
    const int base = blockIdx.y * 64;
    if (base >= cnt) return;

    __shared__ float Wst[8][256];
    __shared__ float bcs[8];
    const int tid = threadIdx.x;
    const float* W = Wc2 + (size_t)c * 2048;
    for (int idx = tid; idx < 2048; idx += 256) {
        int k = idx >> 3, j = idx & 7;
        Wst[j][k] = W[idx];
    }
    if (tid < 8) bcs[tid] = bc2[c * 8 + tid];
    __syncthreads();

    const int warp = tid >> 5, lane = tid & 31;
    for (int u = 0; u < 8; u++) {
        int gi = base + u * 8 + warp;
        if (gi >= cnt) break;                 // warp-uniform
        int s = g_idx[c * Bn + gi];
        const float* hrow = Hbuf + (size_t)s * 256;
        float acc[8];
        #pragma unroll
        for (int j = 0; j < 8; j++) acc[j] = 0.f;
        #pragma unroll
        for (int kk = 0; kk < 256; kk += 32) {
            float hv = hrow[kk + lane];
            #pragma unroll
            for (int j = 0; j < 8; j++) acc[j] += hv * Wst[j][kk + lane];
        }
        #pragma unroll
        for (int j = 0; j < 8; j++)
            #pragma unroll
            for (int off = 16; off; off >>= 1)
                acc[j] += __shfl_down_sync(0xffffffffu, acc[j], off);
        if (lane == 0) {
            float* lo = outLogits + (size_t)s * 8;
            #pragma unroll
            for (int j = 0; j < 8; j++) lo[j] = acc[j] + bcs[j];
        }
    }
}

// ---------------------------------------------------------------------------
// Launch. Inputs (metadata order): x, W1, b1, W2, b2, Wc1, bc1, Wc2, bc2, tau
// Output: [out_logits (B*8) | out_h (B*256) | depths (B)] as float32
// ---------------------------------------------------------------------------
extern "C" void kernel_launch(void* const* d_in, const int* in_sizes, int n_in,
                              void* d_out, int out_size)
{
    const float* x   = (const float*)d_in[0];
    const float* W1  = (const float*)d_in[1];
    const float* b1  = (const float*)d_in[2];
    const float* W2  = (const float*)d_in[3];
    const float* b2  = (const float*)d_in[4];
    const float* Wc1 = (const float*)d_in[5];
    const float* bc1 = (const float*)d_in[6];
    const float* Wc2 = (const float*)d_in[7];
    const float* bc2 = (const float*)d_in[8];
    const float* tau = (const float*)d_in[9];

    float* out       = (float*)d_out;
    float* outLogits = out;
    float* outH      = out + (size_t)Bn * Cc;
    float* outDepth  = out + (size_t)Bn * (Cc + Hh);

    zero_cnt_kernel<<<1, 32>>>();

    // Root: h = relu(x @ W1 + b1) -> out_h
    gemm64x256_relu<false><<<dim3(1, Bn / 64, 1), 256>>>(x, W1, b1, outH);

    // Head logits + softmax + routing + compaction
    head_route<<<Bn / 8, 256>>>(outH, W2, b2, tau, outLogits, outDepth);

    // Expert dense: h_c = relu(h @ Wc1[c] + bc1[c]) for routed rows, in place
    gemm64x256_relu<true><<<dim3(1, Bn / 64, Cc), 256>>>(outH, Wc1, bc1, outH);

    // Expert head: overwrite logits for routed rows
    expert_head<<<dim3(1, Bn / 64, Cc), 256>>>(outH, Wc2, bc2, outLogits);
}